// round 8
// baseline (speedup 1.0000x reference)
#include <cuda_runtime.h>

// ============================================================================
// Layer_70411693850653 — equivariant GNN layer, fully fused. (R5 base + R8)
//
//  * messages[384:640] never consumed -> skipped
//  * agg == 1.5 * feats[:, :128] -> skip connection folded into weights
//  * scatter_mean via bucketed inverse-CSR + register gather (no float atomics)
//  * bucket stores {sender, edge} -> no random senders[] gather in hot loop
//  * R8: quad-packed smem weights (24 instead of 96 weight-load instrs/warp)
//  * R8: next-tile (deg,bucket,sh) prefetched before Phase B -> latency of the
//    serial gather chain hidden under Phase B compute
//  * TILE=8, ~36KB smem, 6 blocks/SM; Phase B scalar FFMA (measured-best form)
// ============================================================================

#define N_MAX 50000
#define CAP   32
#define TILE  8
#define FS    384
#define NBLK  888         // 6 per SM on 148 SMs

__device__ int  g_deg[N_MAX];            // zero-init at load; k_main resets
__device__ int2 g_bucket[N_MAX * CAP];   // {sender, edge}

// ---------------------------------------------------------------------------
__global__ void k_fill(const int* __restrict__ recv,
                       const int* __restrict__ senders, int E) {
    int e = blockIdx.x * blockDim.x + threadIdx.x;
    if (e < E) {
        int r = recv[e];
        int slot = atomicAdd(&g_deg[r], 1);
        if (slot < CAP) g_bucket[r * CAP + slot] = make_int2(senders[e], e);
    }
}

// ---------------------------------------------------------------------------
__global__ void __launch_bounds__(256, 6) k_main(
    const float* __restrict__ nf, const float* __restrict__ sh,
    const float* __restrict__ W0, const float* __restrict__ W1,
    const float* __restrict__ Ws0, const float* __restrict__ Ws1,
    float* __restrict__ out, int N)
{
    // weights as u-quads: sWq[q*32 + lane] = {W[4q][lane], .., W[4q+3][lane]}
    __shared__ __align__(16) float4 sW0q[24 * 32];
    __shared__ __align__(16) float4 sW1q[24 * 32];
    __shared__ __align__(16) float  sF[TILE * FS];

    const float invA = 0.10206207261596575f;         // 1/sqrt(96)
    const float cB   = 1.5f * 0.17677669529663687f;  // 1.5/sqrt(32)
    const float INV_SQRT3 = 0.5773502691896258f;

    const int t    = threadIdx.x;
    const int w    = t >> 5;
    const int lane = t & 31;

    // Effective weights (skip folded), packed into quads
    for (int i = t; i < 24 * 32; i += 256) {
        int q = i >> 5, l = i & 31;
        float4 a, b;
        float* pa = &a.x; float* pb = &b.x;
        #pragma unroll
        for (int k = 0; k < 4; k++) {
            int u = 4 * q + k;
            float w0 = W0[u * 32 + l] * invA;
            float w1 = W1[u * 32 + l] * invA;
            if (u < 32) { w0 = fmaf(cB, Ws0[u * 32 + l], w0);
                          w1 = fmaf(cB, Ws1[u * 32 + l], w1); }
            pa[k] = w0; pb[k] = w1;
        }
        sW0q[i] = a;
        sW1q[i] = b;
    }

    // Phase B role (loop-invariant)
    const float4* Wq;
    int nodeBase, cc;
    if (w < 2) { Wq = sW0q; nodeBase = w * 4; cc = -1; }
    else       { cc = (w - 2) >> 1; nodeBase = ((w - 2) & 1) * 4; Wq = sW1q; }

    const int ntiles = (N + TILE - 1) / TILE;

    // ---- prefetch state for the first tile -------------------------------
    int    pf_d  = 0;
    int    pf_s  = 0;
    float4 pf_sh = make_float4(0.f, 0.f, 0.f, 0.f);
    {
        int n = blockIdx.x * TILE + w;
        if (n < N) {
            pf_d = g_deg[n];
            if (lane == 0) g_deg[n] = 0;           // maintain zero-invariant
            int dcp = min(pf_d, CAP);
            if (lane < dcp) {
                int2 se = g_bucket[n * CAP + lane];
                pf_s    = se.x;
                pf_sh   = *reinterpret_cast<const float4*>(sh + (size_t)se.y * 4);
            }
        }
    }

    for (int tile = blockIdx.x; tile < ntiles; tile += gridDim.x) {
        __syncthreads();   // protect sF against previous iteration's readers

        // ---------------- Phase A: warp w owns node tile*8 + w -------------
        {
            const int d  = pf_d;
            const int dc = min(d, CAP);
            const int    my_s  = pf_s;
            const float4 my_sh = pf_sh;

            float a0 = 0.f, ax = 0.f, ay = 0.f, az = 0.f;
            float p00 = 0.f, dot = 0.f;
            float qx = 0.f, qy = 0.f, qz = 0.f;   // p01 = s0*f1
            float rx = 0.f, ry = 0.f, rz = 0.f;   // p10 = f0*s1

            for (int j = 0; j < dc; j++) {
                int   s   = __shfl_sync(0xffffffffu, my_s,    j);
                float s0  = __shfl_sync(0xffffffffu, my_sh.x, j);
                float s1x = __shfl_sync(0xffffffffu, my_sh.y, j);
                float s1y = __shfl_sync(0xffffffffu, my_sh.z, j);
                float s1z = __shfl_sync(0xffffffffu, my_sh.w, j);

                const float* row = nf + (size_t)s * 128;
                float f0 = __ldg(row + lane);
                float g0 = __ldg(row + 32 + 3 * lane);
                float g1 = __ldg(row + 33 + 3 * lane);
                float g2 = __ldg(row + 34 + 3 * lane);

                a0 += f0; ax += g0; ay += g1; az += g2;
                p00 = fmaf(s0, f0, p00);
                dot = fmaf(s1x, g0, fmaf(s1y, g1, fmaf(s1z, g2, dot)));
                qx  = fmaf(s0, g0, qx);
                qy  = fmaf(s0, g1, qy);
                qz  = fmaf(s0, g2, qz);
                rx  = fmaf(f0, s1x, rx);
                ry  = fmaf(f0, s1y, ry);
                rz  = fmaf(f0, s1z, rz);
            }

            const float scale = 1.0f / (1.5f * (float)max(d, 1));
            float* F = sF + w * FS;
            F[        lane] = a0 * scale;
            F[ 32   + lane] = ax * scale;
            F[ 64   + lane] = ay * scale;
            F[ 96   + lane] = az * scale;
            F[128   + lane] = p00 * scale;
            F[160   + lane] = dot * scale * INV_SQRT3;
            F[192   + lane] = qx * scale;   // c=0: p01
            F[224   + lane] = rx * scale;   // c=0: p10
            F[256   + lane] = qy * scale;   // c=1
            F[288   + lane] = ry * scale;
            F[320   + lane] = qz * scale;   // c=2
            F[352   + lane] = rz * scale;
        }

        // ---- prefetch NEXT tile's gather state (overlaps with Phase B) ----
        {
            pf_d = 0; pf_s = 0;
            pf_sh = make_float4(0.f, 0.f, 0.f, 0.f);
            int n = (tile + gridDim.x) * TILE + w;
            if (tile + gridDim.x < ntiles && n < N) {
                pf_d = g_deg[n];
                if (lane == 0) g_deg[n] = 0;
                int dcp = min(pf_d, CAP);
                if (lane < dcp) {
                    int2 se = g_bucket[n * CAP + lane];
                    pf_s    = se.x;
                    pf_sh   = *reinterpret_cast<const float4*>(sh + (size_t)se.y * 4);
                }
            }
        }
        __syncthreads();

        // ---------------- Phase B: 32 rows (8 nodes x 4) / 8 warps ---------
        const float* pA = (cc < 0) ? (sF + nodeBase * FS)
                                   : (sF + nodeBase * FS + 32 + 32 * cc);
        const float* pB = (cc < 0) ? (sF + nodeBase * FS + 128)
                                   : (sF + nodeBase * FS + 192 + 64 * cc);

        float acc[4];
        #pragma unroll
        for (int r = 0; r < 4; r++) acc[r] = 0.f;

        #pragma unroll
        for (int q = 0; q < 8; q++) {            // u in [0,32)
            float4 wv = Wq[q * 32 + lane];
            #pragma unroll
            for (int r = 0; r < 4; r++) {
                float4 a = *reinterpret_cast<const float4*>(pA + r * FS + 4 * q);
                acc[r] = fmaf(a.x, wv.x, fmaf(a.y, wv.y,
                         fmaf(a.z, wv.z, fmaf(a.w, wv.w, acc[r]))));
            }
        }
        #pragma unroll
        for (int q = 0; q < 16; q++) {           // u in [32,96)
            float4 wv = Wq[(8 + q) * 32 + lane];
            #pragma unroll
            for (int r = 0; r < 4; r++) {
                float4 a = *reinterpret_cast<const float4*>(pB + r * FS + 4 * q);
                acc[r] = fmaf(a.x, wv.x, fmaf(a.y, wv.y,
                         fmaf(a.z, wv.z, fmaf(a.w, wv.w, acc[r]))));
            }
        }

        #pragma unroll
        for (int r = 0; r < 4; r++) {
            int n = tile * TILE + nodeBase + r;
            if (n < N) {
                if (cc < 0) out[(size_t)n * 128 + lane] = acc[r];
                else        out[(size_t)n * 128 + 32 + 3 * lane + cc] = acc[r];
            }
        }
    }
}

// ---------------------------------------------------------------------------
extern "C" void kernel_launch(void* const* d_in, const int* in_sizes, int n_in,
                              void* d_out, int out_size)
{
    const float* nf       = (const float*)d_in[0];
    const float* sh       = (const float*)d_in[1];
    const int*   senders  = (const int*)  d_in[2];
    const int*   recv     = (const int*)  d_in[3];
    const float* W0       = (const float*)d_in[4];
    const float* W1       = (const float*)d_in[5];
    const float* Ws0      = (const float*)d_in[6];
    const float* Ws1      = (const float*)d_in[7];
    float* out = (float*)d_out;

    int N = in_sizes[0] / 128;
    int E = in_sizes[2];

    k_fill<<<(E + 511) / 512, 512>>>(recv, senders, E);
    k_main<<<NBLK, 256>>>(nf, sh, W0, W1, Ws0, Ws1, out, N);
}

// round 9
// speedup vs baseline: 1.9085x; 1.9085x over previous
#include <cuda_runtime.h>

// ============================================================================
// Layer_70411693850653 — equivariant GNN layer, fully fused. (R5 + quad W)
//
//  * messages[384:640] never consumed -> skipped
//  * agg == 1.5 * feats[:, :128] -> skip connection folded into weights
//  * scatter_mean via bucketed inverse-CSR + register gather (no float atomics)
//  * bucket stores {sender, edge} -> no random senders[] gather in hot loop
//  * R9: quad-packed smem weights (24 LDS.128 instead of 96 LDS.32 per
//    warp-tile) — only change vs the 90.1us R5 champion
//  * TILE=8, ~36KB smem, 6 blocks/SM; Phase B scalar FFMA (measured-best form)
// ============================================================================

#define N_MAX 50000
#define CAP   32
#define TILE  8
#define FS    384
#define NBLK  888         // 6 per SM on 148 SMs

__device__ int  g_deg[N_MAX];            // zero-init at load; k_main resets
__device__ int2 g_bucket[N_MAX * CAP];   // {sender, edge}

// ---------------------------------------------------------------------------
__global__ void k_fill(const int* __restrict__ recv,
                       const int* __restrict__ senders, int E) {
    int e = blockIdx.x * blockDim.x + threadIdx.x;
    if (e < E) {
        int r = recv[e];
        int slot = atomicAdd(&g_deg[r], 1);
        if (slot < CAP) g_bucket[r * CAP + slot] = make_int2(senders[e], e);
    }
}

// ---------------------------------------------------------------------------
__global__ void __launch_bounds__(256, 6) k_main(
    const float* __restrict__ nf, const float* __restrict__ sh,
    const float* __restrict__ W0, const float* __restrict__ W1,
    const float* __restrict__ Ws0, const float* __restrict__ Ws1,
    float* __restrict__ out, int N)
{
    // weights as u-quads: sWq[q*32 + lane] = {W[4q][lane], .., W[4q+3][lane]}
    __shared__ __align__(16) float4 sW0q[24 * 32];
    __shared__ __align__(16) float4 sW1q[24 * 32];
    __shared__ __align__(16) float  sF[TILE * FS];

    const float invA = 0.10206207261596575f;         // 1/sqrt(96)
    const float cB   = 1.5f * 0.17677669529663687f;  // 1.5/sqrt(32)
    const float INV_SQRT3 = 0.5773502691896258f;

    const int t    = threadIdx.x;
    const int w    = t >> 5;
    const int lane = t & 31;

    // Effective weights (skip folded), packed into quads
    for (int i = t; i < 24 * 32; i += 256) {
        int q = i >> 5, l = i & 31;
        float4 a, b;
        float* pa = &a.x; float* pb = &b.x;
        #pragma unroll
        for (int k = 0; k < 4; k++) {
            int u = 4 * q + k;
            float w0 = W0[u * 32 + l] * invA;
            float w1 = W1[u * 32 + l] * invA;
            if (u < 32) { w0 = fmaf(cB, Ws0[u * 32 + l], w0);
                          w1 = fmaf(cB, Ws1[u * 32 + l], w1); }
            pa[k] = w0; pb[k] = w1;
        }
        sW0q[i] = a;
        sW1q[i] = b;
    }

    const int ntiles = (N + TILE - 1) / TILE;
    for (int tile = blockIdx.x; tile < ntiles; tile += gridDim.x) {
        __syncthreads();   // protect sF against previous iteration's readers

        // ---------------- Phase A: warp w owns node tile*8 + w -------------
        {
            const int n = tile * TILE + w;

            float a0 = 0.f, ax = 0.f, ay = 0.f, az = 0.f;
            float p00 = 0.f, dot = 0.f;
            float qx = 0.f, qy = 0.f, qz = 0.f;   // p01 = s0*f1
            float rx = 0.f, ry = 0.f, rz = 0.f;   // p10 = f0*s1

            int d = 0;
            if (n < N) d = g_deg[n];
            const int dc = min(d, CAP);
            if (n < N && lane == 0) g_deg[n] = 0;   // maintain zero-invariant

            int    my_s  = 0;
            float4 my_sh = make_float4(0.f, 0.f, 0.f, 0.f);
            if (lane < dc) {
                int2 se = g_bucket[n * CAP + lane];
                my_s    = se.x;
                my_sh   = *reinterpret_cast<const float4*>(sh + (size_t)se.y * 4);
            }

            for (int j = 0; j < dc; j++) {
                int   s   = __shfl_sync(0xffffffffu, my_s,    j);
                float s0  = __shfl_sync(0xffffffffu, my_sh.x, j);
                float s1x = __shfl_sync(0xffffffffu, my_sh.y, j);
                float s1y = __shfl_sync(0xffffffffu, my_sh.z, j);
                float s1z = __shfl_sync(0xffffffffu, my_sh.w, j);

                const float* row = nf + (size_t)s * 128;
                float f0 = row[lane];
                float g0 = row[32 + 3 * lane];
                float g1 = row[33 + 3 * lane];
                float g2 = row[34 + 3 * lane];

                a0 += f0; ax += g0; ay += g1; az += g2;
                p00 = fmaf(s0, f0, p00);
                dot = fmaf(s1x, g0, fmaf(s1y, g1, fmaf(s1z, g2, dot)));
                qx  = fmaf(s0, g0, qx);
                qy  = fmaf(s0, g1, qy);
                qz  = fmaf(s0, g2, qz);
                rx  = fmaf(f0, s1x, rx);
                ry  = fmaf(f0, s1y, ry);
                rz  = fmaf(f0, s1z, rz);
            }

            const float scale = 1.0f / (1.5f * (float)max(d, 1));
            float* F = sF + w * FS;
            F[        lane] = a0 * scale;
            F[ 32   + lane] = ax * scale;
            F[ 64   + lane] = ay * scale;
            F[ 96   + lane] = az * scale;
            F[128   + lane] = p00 * scale;
            F[160   + lane] = dot * scale * INV_SQRT3;
            F[192   + lane] = qx * scale;   // c=0: p01
            F[224   + lane] = rx * scale;   // c=0: p10
            F[256   + lane] = qy * scale;   // c=1
            F[288   + lane] = ry * scale;
            F[320   + lane] = qz * scale;   // c=2
            F[352   + lane] = rz * scale;
        }
        __syncthreads();

        // ---------------- Phase B: 32 rows (8 nodes x 4) / 8 warps ---------
        const float4* Wq;
        int nodeBase, cc;
        if (w < 2) { Wq = sW0q; nodeBase = w * 4; cc = -1; }
        else       { cc = (w - 2) >> 1; nodeBase = ((w - 2) & 1) * 4; Wq = sW1q; }

        const float* pA = (cc < 0) ? (sF + nodeBase * FS)
                                   : (sF + nodeBase * FS + 32 + 32 * cc);
        const float* pB = (cc < 0) ? (sF + nodeBase * FS + 128)
                                   : (sF + nodeBase * FS + 192 + 64 * cc);

        float acc[4];
        #pragma unroll
        for (int r = 0; r < 4; r++) acc[r] = 0.f;

        #pragma unroll
        for (int q = 0; q < 8; q++) {            // u in [0,32)
            float4 wv = Wq[q * 32 + lane];
            #pragma unroll
            for (int r = 0; r < 4; r++) {
                float4 a = *reinterpret_cast<const float4*>(pA + r * FS + 4 * q);
                acc[r] = fmaf(a.x, wv.x, fmaf(a.y, wv.y,
                         fmaf(a.z, wv.z, fmaf(a.w, wv.w, acc[r]))));
            }
        }
        #pragma unroll
        for (int q = 0; q < 16; q++) {           // u in [32,96)
            float4 wv = Wq[(8 + q) * 32 + lane];
            #pragma unroll
            for (int r = 0; r < 4; r++) {
                float4 a = *reinterpret_cast<const float4*>(pB + r * FS + 4 * q);
                acc[r] = fmaf(a.x, wv.x, fmaf(a.y, wv.y,
                         fmaf(a.z, wv.z, fmaf(a.w, wv.w, acc[r]))));
            }
        }

        #pragma unroll
        for (int r = 0; r < 4; r++) {
            int n = tile * TILE + nodeBase + r;
            if (n < N) {
                if (cc < 0) out[(size_t)n * 128 + lane] = acc[r];
                else        out[(size_t)n * 128 + 32 + 3 * lane + cc] = acc[r];
            }
        }
    }
}

// ---------------------------------------------------------------------------
extern "C" void kernel_launch(void* const* d_in, const int* in_sizes, int n_in,
                              void* d_out, int out_size)
{
    const float* nf       = (const float*)d_in[0];
    const float* sh       = (const float*)d_in[1];
    const int*   senders  = (const int*)  d_in[2];
    const int*   recv     = (const int*)  d_in[3];
    const float* W0       = (const float*)d_in[4];
    const float* W1       = (const float*)d_in[5];
    const float* Ws0      = (const float*)d_in[6];
    const float* Ws1      = (const float*)d_in[7];
    float* out = (float*)d_out;

    int N = in_sizes[0] / 128;
    int E = in_sizes[2];

    k_fill<<<(E + 511) / 512, 512>>>(recv, senders, E);
    k_main<<<NBLK, 256>>>(nf, sh, W0, W1, Ws0, Ws1, out, N);
}

// round 10
// speedup vs baseline: 1.9430x; 1.0181x over previous
#include <cuda_runtime.h>

// ============================================================================
// Layer_70411693850653 — equivariant GNN layer, fully fused. (R9 + u-split)
//
//  * messages[384:640] never consumed -> skipped
//  * agg == 1.5 * feats[:, :128] -> skip connection folded into weights
//  * scatter_mean via bucketed inverse-CSR + register gather (no float atomics)
//  * quad-packed smem weights (LDS.128)
//  * R10: Phase B warp PAIRS split the u-reduction (48 u each) over 8 rows of
//    one row-type -> weight wavefronts amortized 2x (24 -> 12 wf/row); partial
//    sums exchanged through a reused corner of sF. Phase B L1: 48 -> 38 wf/row.
//  * TILE=8, 37KB smem, 5 blocks/SM
// ============================================================================

#define N_MAX 50000
#define CAP   32
#define TILE  8
#define FS    384
#define NBLK  740         // 5 per SM on 148 SMs

__device__ int  g_deg[N_MAX];            // zero-init at load; k_main resets
__device__ int2 g_bucket[N_MAX * CAP];   // {sender, edge}

// ---------------------------------------------------------------------------
__global__ void k_fill(const int* __restrict__ recv,
                       const int* __restrict__ senders, int E) {
    int e = blockIdx.x * blockDim.x + threadIdx.x;
    if (e < E) {
        int r = recv[e];
        int slot = atomicAdd(&g_deg[r], 1);
        if (slot < CAP) g_bucket[r * CAP + slot] = make_int2(senders[e], e);
    }
}

// ---------------------------------------------------------------------------
__global__ void __launch_bounds__(256, 5) k_main(
    const float* __restrict__ nf, const float* __restrict__ sh,
    const float* __restrict__ W0, const float* __restrict__ W1,
    const float* __restrict__ Ws0, const float* __restrict__ Ws1,
    float* __restrict__ out, int N)
{
    // weights as u-quads: sWq[q*32 + lane] = {W[4q][lane], .., W[4q+3][lane]}
    __shared__ __align__(16) float4 sW0q[24 * 32];
    __shared__ __align__(16) float4 sW1q[24 * 32];
    __shared__ __align__(16) float  sF[TILE * FS];

    const float invA = 0.10206207261596575f;         // 1/sqrt(96)
    const float cB   = 1.5f * 0.17677669529663687f;  // 1.5/sqrt(32)
    const float INV_SQRT3 = 0.5773502691896258f;

    const int t    = threadIdx.x;
    const int w    = t >> 5;
    const int lane = t & 31;

    // Effective weights (skip folded), packed into quads
    for (int i = t; i < 24 * 32; i += 256) {
        int q = i >> 5, l = i & 31;
        float4 a, b;
        float* pa = &a.x; float* pb = &b.x;
        #pragma unroll
        for (int k = 0; k < 4; k++) {
            int u = 4 * q + k;
            float w0 = W0[u * 32 + l] * invA;
            float w1 = W1[u * 32 + l] * invA;
            if (u < 32) { w0 = fmaf(cB, Ws0[u * 32 + l], w0);
                          w1 = fmaf(cB, Ws1[u * 32 + l], w1); }
            pa[k] = w0; pb[k] = w1;
        }
        sW0q[i] = a;
        sW1q[i] = b;
    }

    // Phase B role (loop-invariant): pair owns one row-type over 8 nodes,
    // halves split the u-range.
    const int pair = w >> 1;          // 0=scalar, 1..3 = vector comp pair-1
    const int h    = w & 1;           // 0: u in [0,48), 1: u in [48,96)
    const float4* Wq  = (pair == 0) ? sW0q : sW1q;
    const int     cc  = pair - 1;
    const int     offA = (pair == 0) ? 0   : 32 + 32 * cc;
    const int     offB = (pair == 0) ? 128 : 192 + 64 * cc;

    const int ntiles = (N + TILE - 1) / TILE;
    for (int tile = blockIdx.x; tile < ntiles; tile += gridDim.x) {
        __syncthreads();   // protect sF against previous iteration's readers

        // ---------------- Phase A: warp w owns node tile*8 + w -------------
        {
            const int n = tile * TILE + w;

            float a0 = 0.f, ax = 0.f, ay = 0.f, az = 0.f;
            float p00 = 0.f, dot = 0.f;
            float qx = 0.f, qy = 0.f, qz = 0.f;   // p01 = s0*f1
            float rx = 0.f, ry = 0.f, rz = 0.f;   // p10 = f0*s1

            int d = 0;
            if (n < N) d = g_deg[n];
            const int dc = min(d, CAP);
            if (n < N && lane == 0) g_deg[n] = 0;   // maintain zero-invariant

            int    my_s  = 0;
            float4 my_sh = make_float4(0.f, 0.f, 0.f, 0.f);
            if (lane < dc) {
                int2 se = g_bucket[n * CAP + lane];
                my_s    = se.x;
                my_sh   = *reinterpret_cast<const float4*>(sh + (size_t)se.y * 4);
            }

            for (int j = 0; j < dc; j++) {
                int   s   = __shfl_sync(0xffffffffu, my_s,    j);
                float s0  = __shfl_sync(0xffffffffu, my_sh.x, j);
                float s1x = __shfl_sync(0xffffffffu, my_sh.y, j);
                float s1y = __shfl_sync(0xffffffffu, my_sh.z, j);
                float s1z = __shfl_sync(0xffffffffu, my_sh.w, j);

                const float* row = nf + (size_t)s * 128;
                float f0 = row[lane];
                float g0 = row[32 + 3 * lane];
                float g1 = row[33 + 3 * lane];
                float g2 = row[34 + 3 * lane];

                a0 += f0; ax += g0; ay += g1; az += g2;
                p00 = fmaf(s0, f0, p00);
                dot = fmaf(s1x, g0, fmaf(s1y, g1, fmaf(s1z, g2, dot)));
                qx  = fmaf(s0, g0, qx);
                qy  = fmaf(s0, g1, qy);
                qz  = fmaf(s0, g2, qz);
                rx  = fmaf(f0, s1x, rx);
                ry  = fmaf(f0, s1y, ry);
                rz  = fmaf(f0, s1z, rz);
            }

            const float scale = 1.0f / (1.5f * (float)max(d, 1));
            float* F = sF + w * FS;
            F[        lane] = a0 * scale;
            F[ 32   + lane] = ax * scale;
            F[ 64   + lane] = ay * scale;
            F[ 96   + lane] = az * scale;
            F[128   + lane] = p00 * scale;
            F[160   + lane] = dot * scale * INV_SQRT3;
            F[192   + lane] = qx * scale;   // c=0: p01
            F[224   + lane] = rx * scale;   // c=0: p10
            F[256   + lane] = qy * scale;   // c=1
            F[288   + lane] = ry * scale;
            F[320   + lane] = qz * scale;   // c=2
            F[352   + lane] = rz * scale;
        }
        __syncthreads();

        // ---------------- Phase B: pair computes 8 rows, halves split u ----
        float acc[8];
        #pragma unroll
        for (int r = 0; r < 8; r++) acc[r] = 0.f;

        if (h == 0) {
            #pragma unroll
            for (int q = 0; q < 8; q++) {            // u in [0,32)  (A region)
                float4 wv = Wq[q * 32 + lane];
                #pragma unroll
                for (int r = 0; r < 8; r++) {
                    float4 a = *reinterpret_cast<const float4*>(
                        sF + r * FS + offA + 4 * q);
                    acc[r] = fmaf(a.x, wv.x, fmaf(a.y, wv.y,
                             fmaf(a.z, wv.z, fmaf(a.w, wv.w, acc[r]))));
                }
            }
            #pragma unroll
            for (int q = 0; q < 4; q++) {            // u in [32,48) (B region)
                float4 wv = Wq[(8 + q) * 32 + lane];
                #pragma unroll
                for (int r = 0; r < 8; r++) {
                    float4 a = *reinterpret_cast<const float4*>(
                        sF + r * FS + offB + 4 * q);
                    acc[r] = fmaf(a.x, wv.x, fmaf(a.y, wv.y,
                             fmaf(a.z, wv.z, fmaf(a.w, wv.w, acc[r]))));
                }
            }
        } else {
            #pragma unroll
            for (int q = 4; q < 16; q++) {           // u in [48,96) (B region)
                float4 wv = Wq[(8 + q) * 32 + lane];
                #pragma unroll
                for (int r = 0; r < 8; r++) {
                    float4 a = *reinterpret_cast<const float4*>(
                        sF + r * FS + offB + 4 * q);
                    acc[r] = fmaf(a.x, wv.x, fmaf(a.y, wv.y,
                             fmaf(a.z, wv.z, fmaf(a.w, wv.w, acc[r]))));
                }
            }
        }
        __syncthreads();                              // all sF reads done

        // h=1 parks partials in a reused corner of sF (4KB of 12KB)
        if (h == 1) {
            #pragma unroll
            for (int r = 0; r < 8; r++)
                sF[(pair * 8 + r) * 32 + lane] = acc[r];
        }
        __syncthreads();

        // h=0 combines and stores
        if (h == 0) {
            #pragma unroll
            for (int r = 0; r < 8; r++) {
                int n = tile * TILE + r;
                if (n < N) {
                    float res = acc[r] + sF[(pair * 8 + r) * 32 + lane];
                    if (pair == 0) out[(size_t)n * 128 + lane] = res;
                    else           out[(size_t)n * 128 + 32 + 3 * lane + cc] = res;
                }
            }
        }
    }
}

// ---------------------------------------------------------------------------
extern "C" void kernel_launch(void* const* d_in, const int* in_sizes, int n_in,
                              void* d_out, int out_size)
{
    const float* nf       = (const float*)d_in[0];
    const float* sh       = (const float*)d_in[1];
    const int*   senders  = (const int*)  d_in[2];
    const int*   recv     = (const int*)  d_in[3];
    const float* W0       = (const float*)d_in[4];
    const float* W1       = (const float*)d_in[5];
    const float* Ws0      = (const float*)d_in[6];
    const float* Ws1      = (const float*)d_in[7];
    float* out = (float*)d_out;

    int N = in_sizes[0] / 128;
    int E = in_sizes[2];

    k_fill<<<(E + 511) / 512, 512>>>(recv, senders, E);
    k_main<<<NBLK, 256>>>(nf, sh, W0, W1, Ws0, Ws1, out, N);
}